// round 15
// baseline (speedup 1.0000x reference)
#include <cuda_runtime.h>
#include <cuda_bf16.h>
#include <cstdint>

// RBFSetConv separable: per batch C^T(64x192) = Wy(64x4096) @ P(4096x192),
//   P = [wx | y*wx | t*wx] (mask folded into wx), Wy = wy, w = exp(-50 d^2).
// Tensor path: mma.sync.m16n8k8 tf32 with 3-product error compensation:
//   C = Ah@Bh + Al@Bh + Ah@Bl      (Al@Bl ~ 2^-24, dropped)
// hi/lo split done in REGISTERS after frag load (smem holds fp32 once).
// Double-buffered chunks: prep(c+1) overlaps mma(c), 1 barrier per chunk.
// 256 CTAs = 8 batches x 32 K-splits, 128 points each, 4 chunks of 32.
// Partial tiles -> g_part; last 128 CTAs (monotonic ticket) reduce+finalize.

typedef unsigned long long ull;

#define SPLITS 32
#define CTAS   256
#define TILE   12288                // 64 x 192 floats per partial tile

// per-buffer smem floats: A (wy) [64 gy][pitch 36] then B (P) [32 k][pitch 200]
#define ABUF 2304
#define BBUF 6400
#define BUFS (ABUF + BBUF)          // 8704 floats = 34816 B
#define SMEM_FLOATS (2 * BUFS)      // 69632 B total

#define DEL   0.031746032f          // 2/63
#define ALG   72.134752f            // 50*log2(e)
#define C1C8  36.639880f            // 8 * 100*DEL*log2(e)
#define C2C64 (-4.6528896f)         // 64 * (-50*DEL^2*log2(e))

__device__ float    g_part[CTAS * TILE];   // 12.6 MB scratch
__device__ unsigned g_ctr;                 // monotonic ticket counter

__device__ __forceinline__ float ex2f(float x) {
    float r; asm("ex2.approx.ftz.f32 %0, %1;" : "=f"(r) : "f"(x)); return r;
}
__device__ __forceinline__ float tf32hi(float v) {
    float h; asm("cvt.rna.tf32.f32 %0, %1;" : "=f"(h) : "f"(v)); return h;
}
__device__ __forceinline__ void mma8(float* d, const unsigned* a, const unsigned* b) {
    asm volatile(
        "mma.sync.aligned.m16n8k8.row.col.f32.tf32.tf32.f32 "
        "{%0,%1,%2,%3}, {%4,%5,%6,%7}, {%8,%9}, {%0,%1,%2,%3};"
        : "+f"(d[0]), "+f"(d[1]), "+f"(d[2]), "+f"(d[3])
        : "r"(a[0]), "r"(a[1]), "r"(a[2]), "r"(a[3]), "r"(b[0]), "r"(b[1]));
}
__device__ __forceinline__ void chk1(unsigned v, int& bi, int& bf, int& bh) {
    bi |= (v > 1u);
    bf |= (v != 0u && v != 0x3F800000u);
    unsigned lo = v & 0xFFFFu, hi = v >> 16;
    bh |= (lo != 0u && lo != 0x3F80u) || (hi != 0u && hi != 0x3F80u);
}

__global__ void __launch_bounds__(256, 2)
k_all(const float* __restrict__ xc, const float* __restrict__ yc,
      const float* __restrict__ tc, const void* __restrict__ mask,
      float* __restrict__ out) {
    extern __shared__ float sd[];
    __shared__ int      s_mode;
    __shared__ unsigned s_ticket;
    __shared__ float    s_inv[64];

    const int tid = threadIdx.x;
    const int l   = tid & 31;
    const int w   = tid >> 5;
    const int b   = blockIdx.x >> 5;
    const int s   = blockIdx.x & 31;

    // ---- mask dtype detection (bitwise, 1KB sample, warp 0) ----
    if (tid < 32) {
        const int4* mv = (const int4*)mask;
        int4 a = __ldg(mv + tid);
        int4 c = __ldg(mv + tid + 32);
        int bi = 0, bf = 0, bh = 0;
        chk1((unsigned)a.x, bi, bf, bh); chk1((unsigned)a.y, bi, bf, bh);
        chk1((unsigned)a.z, bi, bf, bh); chk1((unsigned)a.w, bi, bf, bh);
        chk1((unsigned)c.x, bi, bf, bh); chk1((unsigned)c.y, bi, bf, bh);
        chk1((unsigned)c.z, bi, bf, bh); chk1((unsigned)c.w, bi, bf, bh);
        bi = __any_sync(0xFFFFFFFFu, bi);
        bf = __any_sync(0xFFFFFFFFu, bf);
        bh = __any_sync(0xFFFFFFFFu, bh);
        if (tid == 0) s_mode = (!bi) ? 0 : (!bf) ? 1 : (!bh) ? 2 : 3;
    }
    __syncthreads();
    const int mode = s_mode;
    const float Q8 = ex2f(2.0f * C2C64);   // QF^64

    // prep mapping: point p (0..31) x segment seg (0..7); cols = seg + 8j
    const int p   = tid >> 3;
    const int seg = tid & 7;

    float acc[4][3][4];
#pragma unroll
    for (int mb = 0; mb < 4; mb++)
#pragma unroll
        for (int i = 0; i < 3; i++)
#pragma unroll
            for (int q = 0; q < 4; q++) acc[mb][i][q] = 0.0f;

    // ================= prep one chunk into buffer fb =================
    auto prep = [&](int c, float* fb) {
        const int gi = b * 4096 + s * 128 + c * 32 + p;
        float2 pt = ((const float2*)xc)[gi];
        float yv = yc[gi], tv = tc[gi];
        float vm;
        if (mode == 0)      vm = (((const int*)mask)[gi] != 0) ? 0.0f : 1.0f;
        else if (mode == 1) vm = (((const unsigned*)mask)[gi] != 0u) ? 0.0f : 1.0f;
        else if (mode == 2) vm = ((((const unsigned short*)mask)[gi]) != 0) ? 0.0f : 1.0f;
        else                vm = (((const unsigned char*)mask)[gi] != 0) ? 0.0f : 1.0f;

        // ---- wx -> B rows: fb[ABUF + p*200 + {gx, 64+gx, 128+gx}] ----
        {
            float* Bp = fb + ABUF + p * 200;
            float x  = pt.x;
            float jf = ((x + 1.0f) * 31.5f - (float)seg) * 0.125f;
            int jc = __float2int_rn(jf);
            jc = max(0, min(7, jc));
            float d0  = x + 1.0f - (float)(seg + 8 * jc) * DEL;
            float w0  = ex2f(-ALG * d0 * d0) * vm;
            float rup = ex2f( C1C8 * d0 + C2C64);
            float rdn = ex2f(-C1C8 * d0 + C2C64);
            float wv = w0, r = rup;
#pragma unroll
            for (int jj = 0; jj < 8; jj++) {
                int j = jc + jj;
                if (j < 8) {
                    int idx = seg + 8 * j;
                    Bp[idx]       = wv;
                    Bp[idx + 64]  = yv * wv;
                    Bp[idx + 128] = tv * wv;
                }
                wv *= r; r *= Q8;
            }
            wv = w0; r = rdn;
#pragma unroll
            for (int jj = 1; jj < 8; jj++) {
                wv *= r; r *= Q8;
                int j = jc - jj;
                if (j >= 0) {
                    int idx = seg + 8 * j;
                    Bp[idx]       = wv;
                    Bp[idx + 64]  = yv * wv;
                    Bp[idx + 128] = tv * wv;
                }
            }
        }
        // ---- wy -> A rows: fb[(gy)*36 + p] ----
        {
            float x  = pt.y;
            float jf = ((x + 1.0f) * 31.5f - (float)seg) * 0.125f;
            int jc = __float2int_rn(jf);
            jc = max(0, min(7, jc));
            float d0  = x + 1.0f - (float)(seg + 8 * jc) * DEL;
            float w0  = ex2f(-ALG * d0 * d0);
            float rup = ex2f( C1C8 * d0 + C2C64);
            float rdn = ex2f(-C1C8 * d0 + C2C64);
            float wv = w0, r = rup;
#pragma unroll
            for (int jj = 0; jj < 8; jj++) {
                int j = jc + jj;
                if (j < 8) fb[(seg + 8 * j) * 36 + p] = wv;
                wv *= r; r *= Q8;
            }
            wv = w0; r = rdn;
#pragma unroll
            for (int jj = 1; jj < 8; jj++) {
                wv *= r; r *= Q8;
                int j = jc - jj;
                if (j >= 0) fb[(seg + 8 * j) * 36 + p] = wv;
            }
        }
    };

    // ================= mma over one buffer (4 ksteps of k8) =================
    auto mma_phase = [&](const float* fb) {
        const float* Ap = fb;
        const float* Bp = fb + ABUF;
#pragma unroll
        for (int ks = 0; ks < 4; ks++) {
            const int k0 = ks * 8;
            unsigned ah[4][4], al[4][4], bh[3][2], bl[3][2];
            const int abase = (l >> 2) * 36 + k0 + (l & 3);
#pragma unroll
            for (int mb = 0; mb < 4; mb++) {
                int o = abase + mb * 576;
                float v0 = Ap[o], v1 = Ap[o + 288], v2 = Ap[o + 4], v3 = Ap[o + 292];
                float h0 = tf32hi(v0), h1 = tf32hi(v1), h2 = tf32hi(v2), h3 = tf32hi(v3);
                ah[mb][0] = __float_as_uint(h0); al[mb][0] = __float_as_uint(v0 - h0);
                ah[mb][1] = __float_as_uint(h1); al[mb][1] = __float_as_uint(v1 - h1);
                ah[mb][2] = __float_as_uint(h2); al[mb][2] = __float_as_uint(v2 - h2);
                ah[mb][3] = __float_as_uint(h3); al[mb][3] = __float_as_uint(v3 - h3);
            }
            const int bbase = (k0 + (l & 3)) * 200 + (l >> 2);
#pragma unroll
            for (int i = 0; i < 3; i++) {
                int o = bbase + (3 * w + i) * 8;
                float u0 = Bp[o], u1 = Bp[o + 800];
                float g0 = tf32hi(u0), g1 = tf32hi(u1);
                bh[i][0] = __float_as_uint(g0); bl[i][0] = __float_as_uint(u0 - g0);
                bh[i][1] = __float_as_uint(g1); bl[i][1] = __float_as_uint(u1 - g1);
            }
#pragma unroll
            for (int mb = 0; mb < 4; mb++)
#pragma unroll
                for (int i = 0; i < 3; i++) {
                    mma8(acc[mb][i], ah[mb], bh[i]);
                    mma8(acc[mb][i], al[mb], bh[i]);
                    mma8(acc[mb][i], ah[mb], bl[i]);
                }
        }
    };

    // ============ pipelined chunks: 1 barrier each ============
    prep(0, sd);
    __syncthreads();
#pragma unroll 1
    for (int c = 0; c < 4; c++) {
        if (c < 3) prep(c + 1, sd + ((c + 1) & 1) * BUFS);  // overlaps mma(c)
        mma_phase(sd + (c & 1) * BUFS);
        __syncthreads();
    }

    // ================= flush partial tile [gy][192] =================
    {
        float* dst = g_part + (size_t)blockIdx.x * TILE;
#pragma unroll
        for (int mb = 0; mb < 4; mb++)
#pragma unroll
            for (int i = 0; i < 3; i++) {
                int gy = mb * 16 + (l >> 2);
                int n  = (3 * w + i) * 8 + 2 * (l & 3);
                *(float2*)(dst + gy * 192 + n) =
                    make_float2(acc[mb][i][0], acc[mb][i][1]);
                *(float2*)(dst + (gy + 8) * 192 + n) =
                    make_float2(acc[mb][i][2], acc[mb][i][3]);
            }
    }

    // ================= ticket: last 128 CTAs reduce + finalize ==========
    __threadfence();
    __syncthreads();
    if (tid == 0) s_ticket = atomicAdd(&g_ctr, 1u);
    __syncthreads();
    const unsigned tk = s_ticket;
    const unsigned rr = tk & 255u;            // base is a multiple of 256
    if (rr < 128u) return;

    if (tid == 0) {
        const unsigned target = ((tk >> 8) + 1u) << 8;
        while (atomicAdd(&g_ctr, 0u) < target) { }
    }
    __syncthreads();
    __threadfence();

    const int ru = (int)(rr - 128u);          // 0..127, 4 (b,gy) units each
#pragma unroll 1
    for (int jj = 0; jj < 4; jj++) {
        int u   = ru * 4 + jj;
        int ub  = u >> 6, ugy = u & 63;
        float sum = 0.0f;
        if (tid < 192) {
            const float* base = g_part + ((size_t)(ub * SPLITS)) * TILE + ugy * 192 + tid;
#pragma unroll
            for (int sp = 0; sp < SPLITS; sp++)
                sum += base[sp * TILE];
            if (tid < 64) s_inv[tid] = 1.0f / (sum + 1e-5f);
        }
        __syncthreads();
        if (tid < 192) {
            int ch = tid >> 6, gx = tid & 63;
            float v = (ch == 0) ? sum : sum * s_inv[gx];
            out[((ub * 3 + ch) << 12) + (ugy << 6) + gx] = v;
        }
        __syncthreads();
    }
}

extern "C" void kernel_launch(void* const* d_in, const int* in_sizes, int n_in,
                              void* d_out, int out_size) {
    const float* xc   = (const float*)d_in[0];
    const float* yc   = (const float*)d_in[1];
    const float* tc   = (const float*)d_in[2];
    const void*  mask = d_in[3];

    static int smem_set = 0;
    if (!smem_set) {
        cudaFuncSetAttribute(k_all, cudaFuncAttributeMaxDynamicSharedMemorySize,
                             SMEM_FLOATS * 4);
        smem_set = 1;
    }
    k_all<<<CTAS, 256, SMEM_FLOATS * 4>>>(xc, yc, tc, mask, (float*)d_out);
}